// round 1
// baseline (speedup 1.0000x reference)
#include <cuda_runtime.h>
#include <math.h>

#define BATCH 64
#define CH 512
#define WD 512
#define NPIX 16
#define NCOL (CH*NPIX)   /* 8192 */
#define KC 64
#define TN 64

// ---- scratch (allocation-free rule: __device__ globals) ----
__device__ __align__(16) float g_s [BATCH*CH];   // style [b][i]
__device__ __align__(16) float g_sT[CH*BATCH];   // style transposed [i][b]
__device__ __align__(16) float g_U [CH*NCOL];    // U[i][o*16+p]  (16 MB)
__device__ __align__(16) float g_Q [CH*CH];      // Q[i][o]
__device__ __align__(16) float g_d [BATCH*CH];   // demod [b][o]

// ---------------- Kernel A: style dense  s = w0 @ (mod_w/sqrt(512)) + mod_b + 1
__global__ void style_kernel(const float* __restrict__ w0,
                             const float* __restrict__ mod_w,
                             const float* __restrict__ mod_b) {
    __shared__ float w0s[WD];
    int b = blockIdx.x;
    int c = threadIdx.x;          // 512 threads
    w0s[c] = w0[b*WD + c];
    __syncthreads();
    float acc = 0.f;
    #pragma unroll 8
    for (int j = 0; j < WD; j++)
        acc += w0s[j] * mod_w[j*CH + c];
    const float inv = 1.0f / sqrtf((float)WD);
    float s = acc * inv + mod_b[c] + 1.0f;
    g_s[b*CH + c]   = s;
    g_sT[c*BATCH + b] = s;
}

// ---------------- Kernel B: batch-independent U[i,o,p] = conv(const_i, w_rt[:, i, o]) and Q[i,o]
__global__ void precompute_kernel(const float* __restrict__ conv_w,
                                  const float* __restrict__ cst) {
    int i = blockIdx.x;           // input channel
    int o = threadIdx.x;          // 512 threads = output channel
    __shared__ float cs[NPIX];
    if (o < NPIX) cs[o] = cst[i*NPIX + o];
    __syncthreads();

    const float coef = 1.0f / sqrtf(9.0f * (float)CH);  // equalized-lr runtime coef
    float w[9];
    float q = 0.f;
    #pragma unroll
    for (int t = 0; t < 9; t++) {
        float v = conv_w[((size_t)t*CH + i)*CH + o] * coef;  // HWIO, o contiguous -> coalesced
        w[t] = v;
        q += v * v;
    }
    g_Q[i*CH + o] = q;

    float out[16];
    #pragma unroll
    for (int h = 0; h < 4; h++) {
        #pragma unroll
        for (int x = 0; x < 4; x++) {
            float a = 0.f;
            #pragma unroll
            for (int kh = 0; kh < 3; kh++) {
                int hh = h + kh - 1;
                if (hh < 0 || hh >= 4) continue;
                #pragma unroll
                for (int kw = 0; kw < 3; kw++) {
                    int xx = x + kw - 1;
                    if (xx < 0 || xx >= 4) continue;
                    a += w[kh*3+kw] * cs[hh*4 + xx];
                }
            }
            out[h*4 + x] = a;
        }
    }
    float4* dst = (float4*)&g_U[(size_t)i*NCOL + o*NPIX];
    const float4* src = (const float4*)out;
    dst[0] = src[0]; dst[1] = src[1]; dst[2] = src[2]; dst[3] = src[3];
}

// ---------------- Kernel C: demod  d[b,o] = rsqrt( sum_i s[b,i]^2 * Q[i,o] + 1e-8 )
__global__ void demod_kernel() {
    int b = blockIdx.x;
    int o = threadIdx.x;          // 512 threads
    __shared__ float s2[CH];
    float sv = g_s[b*CH + o];
    s2[o] = sv * sv;
    __syncthreads();
    float acc = 1e-8f;
    #pragma unroll 8
    for (int i = 0; i < CH; i++)
        acc += s2[i] * g_Q[i*CH + o];
    g_d[b*CH + o] = rsqrtf(acc);
}

// ---------------- Kernel D: main GEMM Y[b,n] = sum_k s[b,k]*U[k,n], fused epilogue
// grid 128 CTAs (n-tiles of 64), 128 threads; thread tile 8(b) x 4(n)
__global__ __launch_bounds__(128) void main_gemm_kernel(
        const float* __restrict__ noise,     // [B,1,4,4]
        const float* __restrict__ ns_ptr,    // scalar
        const float* __restrict__ bias,      // [C]
        float* __restrict__ out) {           // [B,C,4,4]
    __shared__ float s_s[KC][BATCH];         // sT tile: [k][b]
    __shared__ float u_s[KC][TN + 4];        // U tile, padded (row = 272B, 16B-aligned)

    int tid = threadIdx.x;
    int tx = tid & 15;        // n group (4 cols each)
    int ty = tid >> 4;        // 0..7, b group (8 rows each)
    int n0 = blockIdx.x * TN;

    float acc[8][4];
    #pragma unroll
    for (int a = 0; a < 8; a++)
        #pragma unroll
        for (int c = 0; c < 4; c++) acc[a][c] = 0.f;

    for (int k0 = 0; k0 < CH; k0 += KC) {
        // stage sT tile (64x64 floats, contiguous)
        const float4* sg = (const float4*)&g_sT[k0 * BATCH];
        float4* sd = (float4*)&s_s[0][0];
        #pragma unroll
        for (int q = 0; q < 8; q++)
            sd[tid + q*128] = sg[tid + q*128];
        // stage U tile rows (coalesced float4)
        {
            int row = tid >> 4;
            int col = tid & 15;
            #pragma unroll
            for (int q = 0; q < 8; q++) {
                int r = row + q*8;
                float4 v = *(const float4*)&g_U[(size_t)(k0 + r)*NCOL + n0 + col*4];
                *(float4*)&u_s[r][col*4] = v;
            }
        }
        __syncthreads();

        #pragma unroll
        for (int k = 0; k < KC; k++) {
            float4 uv = *(const float4*)&u_s[k][tx*4];
            float4 sa = *(const float4*)&s_s[k][ty*8];
            float4 sb = *(const float4*)&s_s[k][ty*8 + 4];
            float sv[8] = {sa.x, sa.y, sa.z, sa.w, sb.x, sb.y, sb.z, sb.w};
            float uc[4] = {uv.x, uv.y, uv.z, uv.w};
            #pragma unroll
            for (int a = 0; a < 8; a++)
                #pragma unroll
                for (int c = 0; c < 4; c++)
                    acc[a][c] += sv[a] * uc[c];
        }
        __syncthreads();
    }

    // epilogue: demod, noise, bias, leaky-relu * sqrt(2)
    float nstr = ns_ptr[0];
    int nbase = n0 + tx*4;
    int o = nbase >> 4;                  // constant across the 4 cols
    float bo = bias[o];
    const float gain = 1.41421356237309515f;
    #pragma unroll
    for (int a = 0; a < 8; a++) {
        int b = ty*8 + a;
        float dv = g_d[b*CH + o];
        float vals[4];
        #pragma unroll
        for (int c = 0; c < 4; c++) {
            int p = (nbase + c) & 15;
            float v = acc[a][c] * dv + noise[b*NPIX + p] * nstr + bo;
            v = (v > 0.f) ? v : 0.2f * v;
            vals[c] = v * gain;
        }
        *(float4*)&out[(size_t)b*NCOL + nbase] =
            make_float4(vals[0], vals[1], vals[2], vals[3]);
    }
}

extern "C" void kernel_launch(void* const* d_in, const int* in_sizes, int n_in,
                              void* d_out, int out_size) {
    const float* w0     = (const float*)d_in[0];  // [64,512]
    const float* cst    = (const float*)d_in[1];  // [1,512,4,4]
    const float* conv_w = (const float*)d_in[2];  // [3,3,512,512] HWIO
    const float* mod_w  = (const float*)d_in[3];  // [512,512]
    const float* mod_b  = (const float*)d_in[4];  // [512]
    const float* noise  = (const float*)d_in[5];  // [64,1,4,4]
    const float* nstr   = (const float*)d_in[6];  // scalar
    const float* bias   = (const float*)d_in[7];  // [512]
    float* out = (float*)d_out;                   // [64,512,4,4]

    style_kernel<<<BATCH, CH>>>(w0, mod_w, mod_b);
    precompute_kernel<<<CH, CH>>>(conv_w, cst);
    demod_kernel<<<BATCH, CH>>>();
    main_gemm_kernel<<<NCOL / TN, 128>>>(noise, nstr, bias, out);
}

// round 2
// speedup vs baseline: 1.3455x; 1.3455x over previous
#include <cuda_runtime.h>
#include <math.h>

#define BATCH 64
#define CH 512
#define WD 512
#define NPIX 16
#define NCOL (CH*NPIX)   /* 8192 */
#define KC 64            /* k-tile (input channels per stage) */
#define TN 64            /* n-tile = 4 output channels x 16 px */
#define TM 32            /* m-tile (batch rows per CTA, M split 2) */

// ---- scratch (allocation-free rule: __device__ globals) ----
__device__ __align__(16) float g_sT [CH*BATCH];   // style transposed [i][b]
__device__ __align__(16) float g_s2T[CH*BATCH];   // style^2 transposed [i][b]

// ---------------- Kernel A: style dense  s = w0 @ (mod_w/sqrt(512)) + mod_b + 1
__global__ void style_kernel(const float* __restrict__ w0,
                             const float* __restrict__ mod_w,
                             const float* __restrict__ mod_b) {
    __shared__ float w0s[WD];
    int b = blockIdx.x;
    int c = threadIdx.x;          // 512 threads
    w0s[c] = w0[b*WD + c];
    __syncthreads();
    float acc = 0.f;
    #pragma unroll 8
    for (int j = 0; j < WD; j++)
        acc += w0s[j] * mod_w[j*CH + c];
    const float inv = 1.0f / sqrtf((float)WD);
    float s = acc * inv + mod_b[c] + 1.0f;
    g_sT [c*BATCH + b] = s;
    g_s2T[c*BATCH + b] = s * s;
}

// ---------------- Kernel B: fully fused modconv
// y[b,n] = d[b,o] * sum_i s[b,i]*U[i,n] ; U built on the fly from conv_w+const;
// d from acc2 = sum_i s^2 * q[i,o], q = sum_t w_rt^2.
// grid 256 = 128 n-tiles x 2 m-halves; 128 threads; thread tile 4m x 4n.
__global__ __launch_bounds__(128) void fused_kernel(
        const float* __restrict__ conv_w,    // [3,3,512,512] HWIO
        const float* __restrict__ cst,       // [1,512,4,4]
        const float* __restrict__ noise,     // [B,1,4,4]
        const float* __restrict__ ns_ptr,    // scalar
        const float* __restrict__ bias,      // [C]
        float* __restrict__ out) {           // [B,C,4,4]
    __shared__ float s_s [KC][TM];           // s tile   [k][m]   8KB
    __shared__ float s2_s[KC][TM];           // s^2 tile          8KB
    __shared__ float u_s [KC][TN + 4];       // U tile (padded)  17KB
    __shared__ float cs_s[KC][NPIX];         // const rows        4KB
    __shared__ float w_s [9][KC][4];         // conv_w slice      9KB
    __shared__ float q_s [KC][4];            // q[i][o']          1KB

    const int tid = threadIdx.x;
    const int tx = tid & 15;                 // n-group (4 cols each)
    const int ty = tid >> 4;                 // m-group (4 rows each), 0..7
    const int ntile = blockIdx.x >> 1;
    const int m0 = (blockIdx.x & 1) * TM;
    const int n0 = ntile * TN;
    const int o0 = n0 >> 4;                  // first of 4 output channels

    const float coef = 1.0f / sqrtf(9.0f * (float)CH);

    float acc[4][4];
    float acc2[4];
    #pragma unroll
    for (int a = 0; a < 4; a++) {
        acc2[a] = 0.f;
        #pragma unroll
        for (int c = 0; c < 4; c++) acc[a][c] = 0.f;
    }

    for (int k0 = 0; k0 < CH; k0 += KC) {
        // ---- Phase A: stage s, s^2, const rows, conv_w slice ----
        #pragma unroll
        for (int j = 0; j < 4; j++) {        // 512 float4: s + s2
            int f = tid + j*128;             // 0..511
            int k = f >> 3;                  // 0..63
            int mq = f & 7;                  // 0..7 (x4 floats)
            float4 v = *(const float4*)&g_sT[(k0 + k)*BATCH + m0 + mq*4];
            *(float4*)&s_s[k][mq*4] = v;
            float4 v2 = *(const float4*)&g_s2T[(k0 + k)*BATCH + m0 + mq*4];
            *(float4*)&s2_s[k][mq*4] = v2;
        }
        #pragma unroll
        for (int j = 0; j < 2; j++) {        // 256 float4: const rows
            int f = tid + j*128;
            int i = f >> 2;
            int pq = f & 3;
            float4 v = *(const float4*)&cst[(k0 + i)*NPIX + pq*4];
            *(float4*)&cs_s[i][pq*4] = v;
        }
        for (int f = tid; f < 9*KC; f += 128) {  // 576 float4: conv_w slice
            int t = f >> 6;                  // 0..8
            int i = f & 63;
            float4 v = *(const float4*)&conv_w[((size_t)(t*CH) + (k0 + i))*CH + o0];
            w_s[t][i][0] = v.x * coef;
            w_s[t][i][1] = v.y * coef;
            w_s[t][i][2] = v.z * coef;
            w_s[t][i][3] = v.w * coef;
        }
        __syncthreads();

        // ---- Phase B: build U tile + q ----
        #pragma unroll
        for (int j = 0; j < 2; j++) {
            int f = tid + j*128;             // 0..255 = 64 i x 4 o'
            int i = f >> 2;
            int op = f & 3;
            float w9[9];
            float q = 0.f;
            #pragma unroll
            for (int t = 0; t < 9; t++) {
                float w = w_s[t][i][op];
                w9[t] = w;
                q += w * w;
            }
            q_s[i][op] = q;
            float c16[NPIX];
            #pragma unroll
            for (int p = 0; p < NPIX; p++) c16[p] = cs_s[i][p];
            float u16[NPIX];
            #pragma unroll
            for (int h = 0; h < 4; h++) {
                #pragma unroll
                for (int x = 0; x < 4; x++) {
                    float a = 0.f;
                    #pragma unroll
                    for (int kh = 0; kh < 3; kh++) {
                        int hh = h + kh - 1;
                        if (hh < 0 || hh >= 4) continue;
                        #pragma unroll
                        for (int kw = 0; kw < 3; kw++) {
                            int xx = x + kw - 1;
                            if (xx < 0 || xx >= 4) continue;
                            a += w9[kh*3 + kw] * c16[hh*4 + xx];
                        }
                    }
                    u16[h*4 + x] = a;
                }
            }
            #pragma unroll
            for (int qd = 0; qd < 4; qd++)
                *(float4*)&u_s[i][op*NPIX + qd*4] = *(float4*)&u16[qd*4];
        }
        __syncthreads();

        // ---- Phase C: GEMM micro-loop ----
        #pragma unroll 8
        for (int k = 0; k < KC; k++) {
            float4 sv4  = *(const float4*)&s_s [k][ty*4];
            float4 s2v4 = *(const float4*)&s2_s[k][ty*4];
            float4 uv4  = *(const float4*)&u_s [k][tx*4];
            float  qv   = q_s[k][tx >> 2];
            float sv[4]  = {sv4.x,  sv4.y,  sv4.z,  sv4.w};
            float s2v[4] = {s2v4.x, s2v4.y, s2v4.z, s2v4.w};
            float uv[4]  = {uv4.x,  uv4.y,  uv4.z,  uv4.w};
            #pragma unroll
            for (int a = 0; a < 4; a++) {
                #pragma unroll
                for (int c = 0; c < 4; c++)
                    acc[a][c] += sv[a] * uv[c];
                acc2[a] += s2v[a] * qv;
            }
        }
        __syncthreads();
    }

    // ---- epilogue: demod, noise, bias, leaky-relu * sqrt(2) ----
    const float nstr = ns_ptr[0];
    const int o = o0 + (tx >> 2);
    const float bo = bias[o];
    const float gain = 1.41421356237309515f;
    const int pq = (tx & 3) * 4;             // pixel base within channel
    #pragma unroll
    for (int a = 0; a < 4; a++) {
        int b = m0 + ty*4 + a;
        float dv = rsqrtf(acc2[a] + 1e-8f);
        float4 nz = *(const float4*)&noise[b*NPIX + pq];
        float nzv[4] = {nz.x, nz.y, nz.z, nz.w};
        float vals[4];
        #pragma unroll
        for (int c = 0; c < 4; c++) {
            float v = acc[a][c] * dv + nzv[c] * nstr + bo;
            v = (v > 0.f) ? v : 0.2f * v;
            vals[c] = v * gain;
        }
        *(float4*)&out[(size_t)b*NCOL + n0 + tx*4] =
            make_float4(vals[0], vals[1], vals[2], vals[3]);
    }
}

extern "C" void kernel_launch(void* const* d_in, const int* in_sizes, int n_in,
                              void* d_out, int out_size) {
    const float* w0     = (const float*)d_in[0];  // [64,512]
    const float* cst    = (const float*)d_in[1];  // [1,512,4,4]
    const float* conv_w = (const float*)d_in[2];  // [3,3,512,512] HWIO
    const float* mod_w  = (const float*)d_in[3];  // [512,512]
    const float* mod_b  = (const float*)d_in[4];  // [512]
    const float* noise  = (const float*)d_in[5];  // [64,1,4,4]
    const float* nstr   = (const float*)d_in[6];  // scalar
    const float* bias   = (const float*)d_in[7];  // [512]
    float* out = (float*)d_out;                   // [64,512,4,4]

    style_kernel<<<BATCH, CH>>>(w0, mod_w, mod_b);
    fused_kernel<<<(NCOL / TN) * 2, 128>>>(conv_w, cst, noise, nstr, bias, out);
}

// round 3
// speedup vs baseline: 1.5078x; 1.1206x over previous
#include <cuda_runtime.h>
#include <math.h>

#define BATCH 64
#define CH 512
#define WD 512
#define NPIX 16
#define NCOL (CH*NPIX)   /* 8192 */
#define KC 64            /* k-tile (input channels per stage) */
#define TN 64            /* n-tile = 4 output channels x 16 px */
#define TM 64            /* full batch per CTA */

// ---- scratch (allocation-free rule: __device__ global) ----
__device__ __align__(16) float g_sT[CH*BATCH];   // style transposed [i][b]

// packed fp32x2 FMA (Blackwell paired-fp32)
union F2 { float2 f; unsigned long long u; };
__device__ __forceinline__ void fma2(F2& d, F2 a, F2 b) {
    asm("fma.rn.f32x2 %0, %1, %2, %0;" : "+l"(d.u) : "l"(a.u), "l"(b.u));
}

// ---------------- Kernel A: style dense  s = w0 @ (mod_w/sqrt(512)) + mod_b + 1
// grid 16 CTAs (32 c-cols each, all 64 b), 256 threads. mod_w read exactly once.
__global__ __launch_bounds__(256) void style_kernel(
        const float* __restrict__ w0,
        const float* __restrict__ mod_w,
        const float* __restrict__ mod_b) {
    __shared__ float w0s[64][64];    // [b][j] 16KB
    __shared__ float mws[64][32];    // [j][c] 8KB
    const int tid = threadIdx.x;
    const int c  = tid & 31;         // local c
    const int bg = tid >> 5;         // 0..7 (8 b each)
    const int c0 = blockIdx.x * 32;

    float acc[8];
    #pragma unroll
    for (int r = 0; r < 8; r++) acc[r] = 0.f;

    for (int jt = 0; jt < 8; jt++) {
        #pragma unroll
        for (int q = 0; q < 4; q++) {            // w0 tile 64x64
            int f = tid + q*256;
            int b = f >> 4, jq = f & 15;
            *(float4*)&w0s[b][jq*4] =
                *(const float4*)&w0[b*WD + jt*64 + jq*4];
        }
        #pragma unroll
        for (int q = 0; q < 2; q++) {            // mod_w tile 64x32
            int f = tid + q*256;
            int j = f >> 3, cq = f & 7;
            *(float4*)&mws[j][cq*4] =
                *(const float4*)&mod_w[(size_t)(jt*64 + j)*CH + c0 + cq*4];
        }
        __syncthreads();
        #pragma unroll 8
        for (int j = 0; j < 64; j++) {
            float mv = mws[j][c];
            #pragma unroll
            for (int r = 0; r < 8; r++)
                acc[r] += w0s[bg*8 + r][j] * mv;
        }
        __syncthreads();
    }
    const float inv = 1.0f / sqrtf((float)WD);
    float bb = mod_b[c0 + c];
    #pragma unroll
    for (int r = 0; r < 8; r++)
        g_sT[(size_t)(c0 + c)*BATCH + bg*8 + r] = acc[r]*inv + bb + 1.0f;
}

// ---------------- Kernel B: fully fused modconv
// grid 128 (one n-tile of 64 each, full M=64), 256 threads.
// thread tile 8m x 2n, m packed as f32x2 pairs.
__global__ __launch_bounds__(256) void fused_kernel(
        const float* __restrict__ conv_w,    // [3,3,512,512] HWIO
        const float* __restrict__ cst,       // [1,512,4,4]
        const float* __restrict__ noise,     // [B,1,4,4]
        const float* __restrict__ ns_ptr,    // scalar
        const float* __restrict__ bias,      // [C]
        float* __restrict__ out) {           // [B,C,4,4]
    __shared__ float s_s [KC][TM];           // s tile [k][m]     16KB
    __shared__ float u_s [KC][TN + 4];       // U tile (padded)   17KB
    __shared__ float cs_s[KC][NPIX];         // const rows         4KB
    __shared__ float w_s [9][KC][4];         // conv_w slice       9KB
    __shared__ float q_s [KC*4];             // q[k][og]; reused as d[og][m]  1KB

    const int tid = threadIdx.x;
    const int tx = tid & 31;                 // n-group (2 cols each)
    const int ty = tid >> 5;                 // 0..7, m-group (8 rows each)
    const int n0 = blockIdx.x * TN;
    const int o0 = n0 >> 4;                  // first of 4 output channels
    const int dm = tid & 63;                 // demod-phase m
    const int dg = tid >> 6;                 // demod-phase o-group 0..3

    const float coef = 1.0f / sqrtf(9.0f * (float)CH);

    F2 acc[4][2];
    #pragma unroll
    for (int a = 0; a < 4; a++)
        #pragma unroll
        for (int c = 0; c < 2; c++) { acc[a][c].f.x = 0.f; acc[a][c].f.y = 0.f; }
    float acc2 = 0.f;

    for (int k0 = 0; k0 < CH; k0 += KC) {
        // ---- stage s tile, const rows, conv_w slice ----
        #pragma unroll
        for (int j = 0; j < 4; j++) {            // 1024 float4
            int f = tid + j*256;
            int k = f >> 4, mq = f & 15;
            *(float4*)&s_s[k][mq*4] =
                *(const float4*)&g_sT[(size_t)(k0 + k)*BATCH + mq*4];
        }
        {                                        // 256 float4 const
            int i = tid >> 2, pq = tid & 3;
            *(float4*)&cs_s[i][pq*4] =
                *(const float4*)&cst[(k0 + i)*NPIX + pq*4];
        }
        for (int f = tid; f < 9*KC; f += 256) {  // 576 float4 conv_w
            int t = f >> 6, i = f & 63;
            float4 v = *(const float4*)&conv_w[((size_t)(t*CH) + (k0 + i))*CH + o0];
            *(float4*)&w_s[t][i][0] =
                make_float4(v.x*coef, v.y*coef, v.z*coef, v.w*coef);
        }
        __syncthreads();

        // ---- build U tile + q (one (i,op) per thread) ----
        {
            int i = tid >> 2, op = tid & 3;
            float w9[9], q = 0.f;
            #pragma unroll
            for (int t = 0; t < 9; t++) {
                float w = w_s[t][i][op];
                w9[t] = w; q += w*w;
            }
            q_s[i*4 + op] = q;
            float c16[NPIX];
            #pragma unroll
            for (int p = 0; p < NPIX; p++) c16[p] = cs_s[i][p];
            float u16[NPIX];
            #pragma unroll
            for (int h = 0; h < 4; h++)
                #pragma unroll
                for (int x = 0; x < 4; x++) {
                    float a = 0.f;
                    #pragma unroll
                    for (int kh = 0; kh < 3; kh++) {
                        int hh = h + kh - 1;
                        if (hh < 0 || hh >= 4) continue;
                        #pragma unroll
                        for (int kw = 0; kw < 3; kw++) {
                            int xx = x + kw - 1;
                            if (xx < 0 || xx >= 4) continue;
                            a += w9[kh*3 + kw] * c16[hh*4 + xx];
                        }
                    }
                    u16[h*4 + x] = a;
                }
            #pragma unroll
            for (int qd = 0; qd < 4; qd++)
                *(float4*)&u_s[i][op*NPIX + qd*4] = *(float4*)&u16[qd*4];
        }
        __syncthreads();

        // ---- main GEMM micro-loop (packed f32x2 over m-pairs) ----
        #pragma unroll 8
        for (int k = 0; k < KC; k++) {
            float4 sa = *(const float4*)&s_s[k][ty*8];
            float4 sb = *(const float4*)&s_s[k][ty*8 + 4];
            float2 u2 = *(const float2*)&u_s[k][tx*2];
            F2 uu0, uu1;
            uu0.f = make_float2(u2.x, u2.x);
            uu1.f = make_float2(u2.y, u2.y);
            F2 p0, p1, p2, p3;
            p0.f = make_float2(sa.x, sa.y);
            p1.f = make_float2(sa.z, sa.w);
            p2.f = make_float2(sb.x, sb.y);
            p3.f = make_float2(sb.z, sb.w);
            fma2(acc[0][0], p0, uu0); fma2(acc[0][1], p0, uu1);
            fma2(acc[1][0], p1, uu0); fma2(acc[1][1], p1, uu1);
            fma2(acc[2][0], p2, uu0); fma2(acc[2][1], p2, uu1);
            fma2(acc[3][0], p3, uu0); fma2(acc[3][1], p3, uu1);
        }

        // ---- demod phase: one (m, og) per thread ----
        {
            float a2 = 0.f;
            #pragma unroll 8
            for (int k = 0; k < KC; k++) {
                float sv = s_s[k][dm];
                a2 = fmaf(sv*sv, q_s[k*4 + dg], a2);
            }
            acc2 += a2;
        }
        __syncthreads();
    }

    // publish demod factors into q_s (reused): d[og][m]
    q_s[dg*64 + dm] = rsqrtf(acc2 + 1e-8f);
    __syncthreads();

    // ---- epilogue: demod, noise, bias, leaky-relu * sqrt(2) ----
    const float nstr = ns_ptr[0];
    const int og = tx >> 3;                  // output channel within tile
    const float bo = bias[o0 + og];
    const int p0x = (tx*2) & 15;             // pixel base
    const float gain = 1.41421356237309515f;
    #pragma unroll
    for (int mp = 0; mp < 4; mp++) {
        #pragma unroll
        for (int h = 0; h < 2; h++) {
            int b = ty*8 + mp*2 + h;
            float dv = q_s[og*64 + b];
            float2 nz = *(const float2*)&noise[b*NPIX + p0x];
            float x0 = (h ? acc[mp][0].f.y : acc[mp][0].f.x) * dv + nz.x*nstr + bo;
            float x1 = (h ? acc[mp][1].f.y : acc[mp][1].f.x) * dv + nz.y*nstr + bo;
            x0 = (x0 > 0.f ? x0 : 0.2f*x0) * gain;
            x1 = (x1 > 0.f ? x1 : 0.2f*x1) * gain;
            *(float2*)&out[(size_t)b*NCOL + n0 + tx*2] = make_float2(x0, x1);
        }
    }
}

extern "C" void kernel_launch(void* const* d_in, const int* in_sizes, int n_in,
                              void* d_out, int out_size) {
    const float* w0     = (const float*)d_in[0];  // [64,512]
    const float* cst    = (const float*)d_in[1];  // [1,512,4,4]
    const float* conv_w = (const float*)d_in[2];  // [3,3,512,512] HWIO
    const float* mod_w  = (const float*)d_in[3];  // [512,512]
    const float* mod_b  = (const float*)d_in[4];  // [512]
    const float* noise  = (const float*)d_in[5];  // [64,1,4,4]
    const float* nstr   = (const float*)d_in[6];  // scalar
    const float* bias   = (const float*)d_in[7];  // [512]
    float* out = (float*)d_out;                   // [64,512,4,4]

    style_kernel<<<16, 256>>>(w0, mod_w, mod_b);
    fused_kernel<<<NCOL / TN, 256>>>(conv_w, cst, noise, nstr, bias, out);
}

// round 5
// speedup vs baseline: 1.6365x; 1.0853x over previous
#include <cuda_runtime.h>
#include <math.h>

#define BATCH 64
#define CH 512
#define WD 512
#define NPIX 16
#define NCOL (CH*NPIX)   /* 8192 */
#define KC 64            /* k-tile */
#define TN 64            /* n-tile = 4 out-ch x 16 px */
#define TM 32            /* m-half per CTA */

// ---- scratch (allocation-free rule: __device__ global) ----
__device__ __align__(16) float g_sT[CH*BATCH];   // style transposed [i][b]

union F2 { float2 f; unsigned long long u; };
__device__ __forceinline__ void fma2(F2& d, F2 a, F2 b) {
    asm("fma.rn.f32x2 %0, %1, %2, %0;" : "+l"(d.u) : "l"(a.u), "l"(b.u));
}

// ---------------- Kernel A: style dense  s = w0 @ (mod_w/sqrt(512)) + mod_b + 1
// grid 64 CTAs (8 c-cols each, all 64 b), 256 threads.
__global__ __launch_bounds__(256) void style_kernel(
        const float* __restrict__ w0,
        const float* __restrict__ mod_w,
        const float* __restrict__ mod_b) {
    __shared__ float w0s[64][68];    // [b][j] padded
    __shared__ float mwsT[8][68];    // [c][j] transposed, padded
    const int tid = threadIdx.x;
    const int c  = tid & 7;          // local c
    const int bg = tid >> 3;         // 0..31 (2 b each)
    const int c0 = blockIdx.x * 8;

    float acc0 = 0.f, acc1 = 0.f;

    for (int jt = 0; jt < 8; jt++) {
        #pragma unroll
        for (int q = 0; q < 4; q++) {            // w0 tile 64x64
            int f = tid + q*256;
            int b = f >> 4, jq = f & 15;
            *(float4*)&w0s[b][jq*4] =
                *(const float4*)&w0[b*WD + jt*64 + jq*4];
        }
        if (tid < 128) {                         // mod_w tile 64j x 8c, transpose
            int j = tid >> 1, cq = tid & 1;
            float4 v = *(const float4*)&mod_w[(size_t)(jt*64 + j)*CH + c0 + cq*4];
            mwsT[cq*4 + 0][j] = v.x;
            mwsT[cq*4 + 1][j] = v.y;
            mwsT[cq*4 + 2][j] = v.z;
            mwsT[cq*4 + 3][j] = v.w;
        }
        __syncthreads();
        #pragma unroll
        for (int j4 = 0; j4 < 16; j4++) {
            float4 mv = *(const float4*)&mwsT[c][j4*4];
            float4 a0 = *(const float4*)&w0s[bg*2    ][j4*4];
            float4 a1 = *(const float4*)&w0s[bg*2 + 1][j4*4];
            acc0 += a0.x*mv.x + a0.y*mv.y + a0.z*mv.z + a0.w*mv.w;
            acc1 += a1.x*mv.x + a1.y*mv.y + a1.z*mv.z + a1.w*mv.w;
        }
        __syncthreads();
    }
    const float inv = 1.0f / sqrtf((float)WD);
    float bb = mod_b[c0 + c] + 1.0f;
    g_sT[(size_t)(c0 + c)*BATCH + bg*2    ] = acc0*inv + bb;
    g_sT[(size_t)(c0 + c)*BATCH + bg*2 + 1] = acc1*inv + bb;
}

// ---------------- Kernel B: fused modconv
// grid 256 = 128 n-tiles x 2 m-halves; 256 threads; thread tile 4m x 2n (f32x2).
// U built in regs from direct (prefetched) global loads; 2 barriers/tile.
__global__ __launch_bounds__(256) void fused_kernel(
        const float* __restrict__ conv_w,    // [3,3,512,512] HWIO
        const float* __restrict__ cst,       // [1,512,4,4]
        const float* __restrict__ noise,     // [B,1,4,4]
        const float* __restrict__ ns_ptr,    // scalar
        const float* __restrict__ bias,      // [C]
        float* __restrict__ out) {           // [B,C,4,4]
    __shared__ float s_s[KC][TM];            // s tile [k][m]     8KB
    __shared__ float u_s[KC][TN + 4];        // U tile (padded)  17KB
    __shared__ float q_s[KC][4];             // q[k][og]; reused as d[og][m] 1KB

    const int tid = threadIdx.x;
    const int tx = tid & 31;                 // n-group (2 cols)
    const int ty = tid >> 5;                 // 0..7, m-group (4 rows)
    const int ntile = blockIdx.x >> 1;
    const int m0 = (blockIdx.x & 1) * TM;
    const int n0 = ntile * TN;
    const int o0 = n0 >> 4;

    // U-build role: one (i, op) per thread
    const int bi = tid >> 2;                 // 0..63 input channel (local)
    const int bo = tid & 3;                  // 0..3 output channel (local)

    const float coef = 1.0f / sqrtf(9.0f * (float)CH);

    F2 acc[2][2];
    #pragma unroll
    for (int a = 0; a < 2; a++)
        #pragma unroll
        for (int c = 0; c < 2; c++) { acc[a][c].f.x = 0.f; acc[a][c].f.y = 0.f; }
    float acc2 = 0.f;

    // prefetch tile 0's conv_w taps + const row into regs
    float w9[9];
    float4 c4[4];
    const float* wp = conv_w + (size_t)bi*CH + o0 + bo;   // advances by KC*CH per tile
    const float4* cp = (const float4*)&cst[bi*NPIX];      // advances by KC rows per tile
    {
        #pragma unroll
        for (int t = 0; t < 9; t++) w9[t] = wp[(size_t)t*CH*CH];
        #pragma unroll
        for (int qd = 0; qd < 4; qd++) c4[qd] = cp[qd];
    }

    for (int kt = 0; kt < 8; kt++) {
        const int k0 = kt * KC;
        __syncthreads();                     // A: prev compute done (s_s/u_s/q_s free)

        // stage s tile (64k x 32m = 512 float4)
        #pragma unroll
        for (int j = 0; j < 2; j++) {
            int f = tid + j*256;
            int k = f >> 3, mq = f & 7;
            *(float4*)&s_s[k][mq*4] =
                *(const float4*)&g_sT[(size_t)(k0 + k)*BATCH + m0 + mq*4];
        }

        // build U row + q from prefetched regs
        {
            float q = 0.f;
            float wr[9];
            #pragma unroll
            for (int t = 0; t < 9; t++) {
                float w = w9[t] * coef;
                wr[t] = w; q += w*w;
            }
            q_s[bi][bo] = q;
            float c16[NPIX];
            *(float4*)&c16[0]  = c4[0]; *(float4*)&c16[4]  = c4[1];
            *(float4*)&c16[8]  = c4[2]; *(float4*)&c16[12] = c4[3];
            float u16[NPIX];
            #pragma unroll
            for (int h = 0; h < 4; h++)
                #pragma unroll
                for (int x = 0; x < 4; x++) {
                    float a = 0.f;
                    #pragma unroll
                    for (int kh = 0; kh < 3; kh++) {
                        int hh = h + kh - 1;
                        if (hh < 0 || hh >= 4) continue;
                        #pragma unroll
                        for (int kw = 0; kw < 3; kw++) {
                            int xx = x + kw - 1;
                            if (xx < 0 || xx >= 4) continue;
                            a += wr[kh*3 + kw] * c16[hh*4 + xx];
                        }
                    }
                    u16[h*4 + x] = a;
                }
            #pragma unroll
            for (int qd = 0; qd < 4; qd++)
                *(float4*)&u_s[bi][bo*NPIX + qd*4] = *(float4*)&u16[qd*4];
        }

        // prefetch next tile's conv_w + const (overlaps barrier + compute)
        if (kt < 7) {
            wp += (size_t)KC * CH;
            cp += KC * (NPIX / 4);
            #pragma unroll
            for (int t = 0; t < 9; t++) w9[t] = wp[(size_t)t*CH*CH];
            #pragma unroll
            for (int qd = 0; qd < 4; qd++) c4[qd] = cp[qd];
        }

        __syncthreads();                     // B: s_s + u_s + q_s ready

        // main GEMM micro-loop: 4m x 2n per thread, m packed in f32x2
        #pragma unroll 8
        for (int k = 0; k < KC; k++) {
            float4 sa = *(const float4*)&s_s[k][ty*4];
            float2 u2 = *(const float2*)&u_s[k][tx*2];
            F2 uu0, uu1, p0, p1;
            uu0.f = make_float2(u2.x, u2.x);
            uu1.f = make_float2(u2.y, u2.y);
            p0.f = make_float2(sa.x, sa.y);
            p1.f = make_float2(sa.z, sa.w);
            fma2(acc[0][0], p0, uu0); fma2(acc[0][1], p0, uu1);
            fma2(acc[1][0], p1, uu0); fma2(acc[1][1], p1, uu1);
        }

        // demod: one (m, og) per thread (first 128 threads)
        if (tid < 128) {
            int dm = tid & 31, dg = tid >> 5;
            float a2 = 0.f;
            #pragma unroll 8
            for (int k = 0; k < KC; k++) {
                float sv = s_s[k][dm];
                a2 = fmaf(sv*sv, q_s[k][dg], a2);
            }
            acc2 += a2;
        }
    }

    __syncthreads();
    // publish demod factors: reuse q_s as d[og][m] (flat 4x32)
    if (tid < 128) {
        int dm = tid & 31, dg = tid >> 5;
        ((float*)q_s)[dg*TM + dm] = rsqrtf(acc2 + 1e-8f);
    }
    __syncthreads();

    // epilogue: demod, noise, bias, leaky-relu * sqrt(2)
    const float nstr = ns_ptr[0];
    const int og = tx >> 3;
    const float bb = bias[o0 + og];
    const int p0x = (tx*2) & 15;
    const float gain = 1.41421356237309515f;
    const float* dvp = (const float*)q_s + og*TM;
    #pragma unroll
    for (int mp = 0; mp < 2; mp++) {
        #pragma unroll
        for (int h = 0; h < 2; h++) {
            int ml = ty*4 + mp*2 + h;
            int b  = m0 + ml;
            float dv = dvp[ml];
            float2 nz = *(const float2*)&noise[b*NPIX + p0x];
            float x0 = (h ? acc[mp][0].f.y : acc[mp][0].f.x) * dv + nz.x*nstr + bb;
            float x1 = (h ? acc[mp][1].f.y : acc[mp][1].f.x) * dv + nz.y*nstr + bb;
            x0 = (x0 > 0.f ? x0 : 0.2f*x0) * gain;
            x1 = (x1 > 0.f ? x1 : 0.2f*x1) * gain;
            *(float2*)&out[(size_t)b*NCOL + n0 + tx*2] = make_float2(x0, x1);
        }
    }
}

extern "C" void kernel_launch(void* const* d_in, const int* in_sizes, int n_in,
                              void* d_out, int out_size) {
    const float* w0     = (const float*)d_in[0];  // [64,512]
    const float* cst    = (const float*)d_in[1];  // [1,512,4,4]
    const float* conv_w = (const float*)d_in[2];  // [3,3,512,512] HWIO
    const float* mod_w  = (const float*)d_in[3];  // [512,512]
    const float* mod_b  = (const float*)d_in[4];  // [512]
    const float* noise  = (const float*)d_in[5];  // [64,1,4,4]
    const float* nstr   = (const float*)d_in[6];  // scalar
    const float* bias   = (const float*)d_in[7];  // [512]
    float* out = (float*)d_out;                   // [64,512,4,4]

    style_kernel<<<64, 256>>>(w0, mod_w, mod_b);
    fused_kernel<<<(NCOL / TN) * 2, 256>>>(conv_w, cst, noise, nstr, bias, out);
}